// round 7
// baseline (speedup 1.0000x reference)
#include <cuda_runtime.h>

// Shapes fixed by the problem: [B=4, C=32, H=1024, W=1024] fp32 -> [B,H,W] fp32
#define CCH 32
#define HH  1024
#define WW  1024
#define RAD 25    // kernel_radius = W // 40 = 25 (window = 51)
#define RPB 2     // rows per block in kernel A
#define PAD 32    // zero-pad rows above/below each image in scratch (>= RAD+1)
#define HP  (HH + 2 * PAD)

// padded scratch: channel-summed + box-w'd intermediate, with zero halo rows
__device__ float g_scratch[4 * HP * WW];

__device__ __forceinline__ float sqrt_approx(float s) {
    float r;
    asm("sqrt.approx.f32 %0, %1;" : "=f"(r) : "f"(s));
    return r;   // sqrt.approx(0) = 0, no NaN guard needed
}

// load one channel's tile: prev row (float4), two cur rows (float4), two left scalars
#define LOADCH(c, P, C0, C1, L0, L1)                                              \
    do {                                                                          \
        const float* r0_ = xb + (size_t)(c) * (HH * WW) + (size_t)h0 * WW;        \
        const float* r1_ = r0_ + WW;                                              \
        P  = has_top ? *reinterpret_cast<const float4*>(r0_ - WW + w0)            \
                     : make_float4(0.f, 0.f, 0.f, 0.f);                           \
        C0 = *reinterpret_cast<const float4*>(r0_ + w0);                          \
        C1 = *reinterpret_cast<const float4*>(r1_ + w0);                          \
        L0 = has_left ? r0_[w0 - 1] : 0.f;                                        \
        L1 = has_left ? r1_[w0 - 1] : 0.f;                                        \
    } while (0)

// gradient-magnitude accumulate for a 2-row tile
#define COMPUTE(P, C0, C1, L0, L1)                                                \
    do {                                                                          \
        float dx0 = (L0)   - (C0).x;                                              \
        float dx1 = (C0).x - (C0).y;                                              \
        float dx2 = (C0).y - (C0).z;                                              \
        float dx3 = (C0).z - (C0).w;                                              \
        float dy0 = (P).x - (C0).x;                                               \
        float dy1 = (P).y - (C0).y;                                               \
        float dy2 = (P).z - (C0).z;                                               \
        float dy3 = (P).w - (C0).w;                                               \
        a00 += sqrt_approx(dx0 * dx0 + dy0 * dy0);                                \
        a01 += sqrt_approx(dx1 * dx1 + dy1 * dy1);                                \
        a02 += sqrt_approx(dx2 * dx2 + dy2 * dy2);                                \
        a03 += sqrt_approx(dx3 * dx3 + dy3 * dy3);                                \
        float ex0 = (L1)   - (C1).x;                                              \
        float ex1 = (C1).x - (C1).y;                                              \
        float ex2 = (C1).y - (C1).z;                                              \
        float ex3 = (C1).z - (C1).w;                                              \
        float ey0 = (C0).x - (C1).x;                                              \
        float ey1 = (C0).y - (C1).y;                                              \
        float ey2 = (C0).z - (C1).z;                                              \
        float ey3 = (C0).w - (C1).w;                                              \
        a10 += sqrt_approx(ex0 * ex0 + ey0 * ey0);                                \
        a11 += sqrt_approx(ex1 * ex1 + ey1 * ey1);                                \
        a12 += sqrt_approx(ex2 * ex2 + ey2 * ey2);                                \
        a13 += sqrt_approx(ex3 * ex3 + ey3 * ey3);                                \
    } while (0)

// ---------------------------------------------------------------------------
// Kernel A: per (b, 2-row tile) — gradient magnitude, channel sum, box-w.
// 2-deep software pipeline: channel c's registers were loaded while channels
// c-2 and c-1 computed (~2 compute blocks of latency slack per load).
// Blocks 0..63 of each image also zero one halo row (fused pad kernel).
// ---------------------------------------------------------------------------
__global__ __launch_bounds__(256) void grad_boxw_kernel(const float* __restrict__ x) {
    const int h0   = blockIdx.x * RPB;
    const int b    = blockIdx.y;
    const int tid  = threadIdx.x;
    const int lane = tid & 31;
    const int wid  = tid >> 5;
    const int w0   = tid << 2;

    // ---- fused halo zeroing ----
    if (blockIdx.x < 2 * PAD) {
        int row  = blockIdx.x;
        int prow = (row < PAD) ? row : (HH + row);
        float4* p = reinterpret_cast<float4*>(g_scratch + ((size_t)b * HP + prow) * WW);
        p[tid] = make_float4(0.f, 0.f, 0.f, 0.f);
    }

    const float* xb = x + (size_t)b * CCH * HH * WW;
    const bool has_top  = (h0 > 0);
    const bool has_left = (w0 > 0);

    float a00 = 0.f, a01 = 0.f, a02 = 0.f, a03 = 0.f;
    float a10 = 0.f, a11 = 0.f, a12 = 0.f, a13 = 0.f;

    // double-buffered channel registers
    float4 Ap, A0, A1; float Al0, Al1;
    float4 Bp, B0, B1; float Bl0, Bl1;

    LOADCH(0, Ap, A0, A1, Al0, Al1);
    LOADCH(1, Bp, B0, B1, Bl0, Bl1);

    for (int c = 0; c < CCH; c += 2) {
        // stash A, immediately refill with channel c+2 (clamped tail: dup loads hit L2)
        float4 p = Ap, q0 = A0, q1 = A1; float m0 = Al0, m1 = Al1;
        int cn = (c + 2 < CCH) ? c + 2 : CCH - 1;
        LOADCH(cn, Ap, A0, A1, Al0, Al1);
        COMPUTE(p, q0, q1, m0, m1);

        // same for B / channel c+1 -> prefetch c+3
        float4 pb = Bp, r0 = B0, r1 = B1; float n0 = Bl0, n1 = Bl1;
        int cm = (c + 3 < CCH) ? c + 3 : CCH - 1;
        LOADCH(cm, Bp, B0, B1, Bl0, Bl1);
        COMPUTE(pb, r0, r1, n0, n1);
    }

    // ---- per-row block prefix sum + box-w, 2 rows sequentially ----
    __shared__ float S[WW + 1];
    __shared__ float wsum[8];

    float* gb = g_scratch + (size_t)b * HP * WW + (size_t)PAD * WW;

    #pragma unroll 1
    for (int r = 0; r < RPB; ++r) {
        float v0 = (r == 0) ? a00 : a10;
        float v1 = (r == 0) ? a01 : a11;
        float v2 = (r == 0) ? a02 : a12;
        float v3 = (r == 0) ? a03 : a13;

        float p0 = v0;
        float p1 = p0 + v1;
        float p2 = p1 + v2;
        float p3 = p2 + v3;
        float t  = p3;

        // inclusive warp scan
        float sc = t;
        #pragma unroll
        for (int o = 1; o < 32; o <<= 1) {
            float v = __shfl_up_sync(0xffffffffu, sc, o);
            if (lane >= o) sc += v;
        }
        if (lane == 31) wsum[wid] = sc;
        __syncthreads();
        if (wid == 0) {
            float wv = (lane < 8) ? wsum[lane] : 0.f;
            float ws = wv;
            #pragma unroll
            for (int o = 1; o < 8; o <<= 1) {
                float v = __shfl_up_sync(0xffffffffu, ws, o);
                if (lane >= o) ws += v;
            }
            if (lane < 8) wsum[lane] = ws - wv;
        }
        __syncthreads();

        float bofs = wsum[wid] + (sc - t);
        if (tid == 0) S[0] = 0.f;
        S[w0 + 1] = bofs + p0;
        S[w0 + 2] = bofs + p1;
        S[w0 + 3] = bofs + p2;
        S[w0 + 4] = bofs + p3;
        __syncthreads();

        float* grow = gb + (size_t)(h0 + r) * WW;
        #pragma unroll
        for (int i = 0; i < 4; ++i) {
            int w  = w0 + i;
            int lo = max(0, w - RAD);
            int hi = min(WW - 1, w + RAD);
            grow[w] = S[hi + 1] - S[lo];
        }
        __syncthreads();
    }
}

// ---------------------------------------------------------------------------
// Kernel B: box filter along h. Scalar columns -> 4x the blocks of the float2
// version (1024 blocks, ~55 warps/SM) at identical total traffic; padded
// scratch keeps the fully-unrolled sliding window branch-free.
// ---------------------------------------------------------------------------
#define HT 16
__global__ __launch_bounds__(256) void boxh_kernel(float* __restrict__ out) {
    const int col = blockIdx.x * 256 + threadIdx.x;  // scalar column
    const int h0  = blockIdx.y * HT;
    const int b   = blockIdx.z;

    const float* gp = g_scratch + ((size_t)b * HP + PAD) * WW + col;  // row 0
    float*       op = out + (size_t)b * HH * WW + col;

    // window init over [h0-RAD, h0+RAD] — in-bounds thanks to halo
    float t0 = 0.f, t1 = 0.f, t2 = 0.f, t3 = 0.f;
    #pragma unroll
    for (int j = 0; j < 48; j += 4) {
        t0 += gp[(size_t)(h0 - RAD + j + 0) * WW];
        t1 += gp[(size_t)(h0 - RAD + j + 1) * WW];
        t2 += gp[(size_t)(h0 - RAD + j + 2) * WW];
        t3 += gp[(size_t)(h0 - RAD + j + 3) * WW];
    }
    t0 += gp[(size_t)(h0 + RAD - 2) * WW];
    t1 += gp[(size_t)(h0 + RAD - 1) * WW];
    t2 += gp[(size_t)(h0 + RAD) * WW];

    float s = (t0 + t1) + (t2 + t3);

    // branch-free sliding window (halo rows are zero)
    #pragma unroll
    for (int i = 0; i < HT; ++i) {
        const int h = h0 + i;
        op[(size_t)h * WW] = s;
        s += gp[(size_t)(h + RAD + 1) * WW] - gp[(size_t)(h - RAD) * WW];
    }
}

// ---------------------------------------------------------------------------

extern "C" void kernel_launch(void* const* d_in, const int* in_sizes, int n_in,
                              void* d_out, int out_size) {
    const float* x = (const float*)d_in[0];
    float* out = (float*)d_out;

    const int n = in_sizes[0];
    const int B = n / (CCH * HH * WW);   // 4

    dim3 gridA(HH / RPB, B);
    grad_boxw_kernel<<<gridA, 256>>>(x);

    dim3 gridB(WW / 256, HH / HT, B);
    boxh_kernel<<<gridB, 256>>>(out);
}

// round 8
// speedup vs baseline: 1.0621x; 1.0621x over previous
#include <cuda_runtime.h>

// Shapes fixed by the problem: [B=4, C=32, H=1024, W=1024] fp32 -> [B,H,W] fp32
#define CCH 32
#define HH  1024
#define WW  1024
#define RAD 25    // kernel_radius = W // 40 = 25 (window = 51)
#define RPB 2     // rows per block in kernel A
#define PAD 32    // zero-pad rows above/below each image in scratch (>= RAD+1)
#define HP  (HH + 2 * PAD)

// padded scratch: channel-summed + box-w'd intermediate, with zero halo rows
__device__ float g_scratch[4 * HP * WW];

__device__ __forceinline__ float sqrt_approx(float s) {
    float r;
    asm("sqrt.approx.f32 %0, %1;" : "=f"(r) : "f"(s));
    return r;   // sqrt.approx(0) = 0, no NaN guard needed
}

// ---------------------------------------------------------------------------
// Kernel A: per (b, 2-row tile) — gradient magnitude, channel sum, box-w.
// 1-deep software pipeline (round-6 proven config): channel c+1's loads are
// issued before channel c's compute. Blocks 0..63 also zero one halo row.
// ---------------------------------------------------------------------------
__global__ __launch_bounds__(256) void grad_boxw_kernel(const float* __restrict__ x) {
    const int h0   = blockIdx.x * RPB;
    const int b    = blockIdx.y;
    const int tid  = threadIdx.x;
    const int lane = tid & 31;
    const int wid  = tid >> 5;
    const int w0   = tid << 2;

    // ---- fused halo zeroing ----
    if (blockIdx.x < 2 * PAD) {
        int row  = blockIdx.x;
        int prow = (row < PAD) ? row : (HH + row);
        float4* p = reinterpret_cast<float4*>(g_scratch + ((size_t)b * HP + prow) * WW);
        p[tid] = make_float4(0.f, 0.f, 0.f, 0.f);
    }

    const float* xb = x + (size_t)b * CCH * HH * WW;
    const bool has_top  = (h0 > 0);
    const bool has_left = (w0 > 0);

    float a00 = 0.f, a01 = 0.f, a02 = 0.f, a03 = 0.f;
    float a10 = 0.f, a11 = 0.f, a12 = 0.f, a13 = 0.f;

    // ---- prologue: loads for channel 0 ----
    const float* row0 = xb + (size_t)h0 * WW;
    const float* row1 = row0 + WW;
    float4 prev = has_top ? *reinterpret_cast<const float4*>(row0 - WW + w0)
                          : make_float4(0.f, 0.f, 0.f, 0.f);
    float4 c0 = *reinterpret_cast<const float4*>(row0 + w0);
    float4 c1 = *reinterpret_cast<const float4*>(row1 + w0);
    float  l0 = has_left ? row0[w0 - 1] : 0.f;
    float  l1 = has_left ? row1[w0 - 1] : 0.f;

    for (int c = 0; c < CCH; ++c) {
        // ---- prefetch next channel (independent of current compute) ----
        float4 nprev = make_float4(0.f, 0.f, 0.f, 0.f);
        float4 nc0, nc1;
        float  nl0 = 0.f, nl1 = 0.f;
        if (c + 1 < CCH) {
            const float* nrow0 = xb + (size_t)(c + 1) * HH * WW + (size_t)h0 * WW;
            const float* nrow1 = nrow0 + WW;
            if (has_top) nprev = *reinterpret_cast<const float4*>(nrow0 - WW + w0);
            nc0 = *reinterpret_cast<const float4*>(nrow0 + w0);
            nc1 = *reinterpret_cast<const float4*>(nrow1 + w0);
            if (has_left) { nl0 = nrow0[w0 - 1]; nl1 = nrow1[w0 - 1]; }
        } else {
            nc0 = nc1 = make_float4(0.f, 0.f, 0.f, 0.f);
        }

        // ---- compute current channel ----
        {
            float dx0 = l0   - c0.x;
            float dx1 = c0.x - c0.y;
            float dx2 = c0.y - c0.z;
            float dx3 = c0.z - c0.w;
            float dy0 = prev.x - c0.x;
            float dy1 = prev.y - c0.y;
            float dy2 = prev.z - c0.z;
            float dy3 = prev.w - c0.w;
            a00 += sqrt_approx(dx0 * dx0 + dy0 * dy0);
            a01 += sqrt_approx(dx1 * dx1 + dy1 * dy1);
            a02 += sqrt_approx(dx2 * dx2 + dy2 * dy2);
            a03 += sqrt_approx(dx3 * dx3 + dy3 * dy3);
        }
        {
            float dx0 = l1   - c1.x;
            float dx1 = c1.x - c1.y;
            float dx2 = c1.y - c1.z;
            float dx3 = c1.z - c1.w;
            float dy0 = c0.x - c1.x;
            float dy1 = c0.y - c1.y;
            float dy2 = c0.z - c1.z;
            float dy3 = c0.w - c1.w;
            a10 += sqrt_approx(dx0 * dx0 + dy0 * dy0);
            a11 += sqrt_approx(dx1 * dx1 + dy1 * dy1);
            a12 += sqrt_approx(dx2 * dx2 + dy2 * dy2);
            a13 += sqrt_approx(dx3 * dx3 + dy3 * dy3);
        }

        prev = nprev; c0 = nc0; c1 = nc1; l0 = nl0; l1 = nl1;
    }

    // ---- per-row block prefix sum + box-w, 2 rows sequentially ----
    __shared__ float S[WW + 1];
    __shared__ float wsum[8];

    float* gb = g_scratch + (size_t)b * HP * WW + (size_t)PAD * WW;

    #pragma unroll 1
    for (int r = 0; r < RPB; ++r) {
        float v0 = (r == 0) ? a00 : a10;
        float v1 = (r == 0) ? a01 : a11;
        float v2 = (r == 0) ? a02 : a12;
        float v3 = (r == 0) ? a03 : a13;

        float p0 = v0;
        float p1 = p0 + v1;
        float p2 = p1 + v2;
        float p3 = p2 + v3;
        float t  = p3;

        // inclusive warp scan
        float sc = t;
        #pragma unroll
        for (int o = 1; o < 32; o <<= 1) {
            float v = __shfl_up_sync(0xffffffffu, sc, o);
            if (lane >= o) sc += v;
        }
        if (lane == 31) wsum[wid] = sc;
        __syncthreads();
        if (wid == 0) {
            float wv = (lane < 8) ? wsum[lane] : 0.f;
            float ws = wv;
            #pragma unroll
            for (int o = 1; o < 8; o <<= 1) {
                float v = __shfl_up_sync(0xffffffffu, ws, o);
                if (lane >= o) ws += v;
            }
            if (lane < 8) wsum[lane] = ws - wv;
        }
        __syncthreads();

        float bofs = wsum[wid] + (sc - t);
        if (tid == 0) S[0] = 0.f;
        S[w0 + 1] = bofs + p0;
        S[w0 + 2] = bofs + p1;
        S[w0 + 3] = bofs + p2;
        S[w0 + 4] = bofs + p3;
        __syncthreads();

        // vectorized STG.128 of the 4 box-w outputs
        float4 o4;
        {
            int w  = w0;
            int lo = max(0, w - RAD);
            int hi = min(WW - 1, w + RAD);
            o4.x = S[hi + 1] - S[lo];
        }
        {
            int w  = w0 + 1;
            int lo = max(0, w - RAD);
            int hi = min(WW - 1, w + RAD);
            o4.y = S[hi + 1] - S[lo];
        }
        {
            int w  = w0 + 2;
            int lo = max(0, w - RAD);
            int hi = min(WW - 1, w + RAD);
            o4.z = S[hi + 1] - S[lo];
        }
        {
            int w  = w0 + 3;
            int lo = max(0, w - RAD);
            int hi = min(WW - 1, w + RAD);
            o4.w = S[hi + 1] - S[lo];
        }
        float* grow = gb + (size_t)(h0 + r) * WW;
        *reinterpret_cast<float4*>(grow + w0) = o4;
        __syncthreads();
    }
}

// ---------------------------------------------------------------------------
// Kernel B: box filter along h. HT=32 amortizes the 51-row window init:
// reads per output row drop from 5.19 to 3.59 rows (99 -> 73 MB L2 traffic,
// which is the binder). Branch-free thanks to zero halo rows.
// ---------------------------------------------------------------------------
#define HT 32
__global__ __launch_bounds__(256) void boxh_kernel(float* __restrict__ out) {
    const int col = blockIdx.x * 256 + threadIdx.x;  // scalar column
    const int h0  = blockIdx.y * HT;
    const int b   = blockIdx.z;

    const float* gp = g_scratch + ((size_t)b * HP + PAD) * WW + col;  // row 0
    float*       op = out + (size_t)b * HH * WW + col;

    // window init over [h0-RAD, h0+RAD] — in-bounds thanks to halo
    float t0 = 0.f, t1 = 0.f, t2 = 0.f, t3 = 0.f;
    #pragma unroll
    for (int j = 0; j < 48; j += 4) {
        t0 += gp[(size_t)(h0 - RAD + j + 0) * WW];
        t1 += gp[(size_t)(h0 - RAD + j + 1) * WW];
        t2 += gp[(size_t)(h0 - RAD + j + 2) * WW];
        t3 += gp[(size_t)(h0 - RAD + j + 3) * WW];
    }
    t0 += gp[(size_t)(h0 + RAD - 2) * WW];
    t1 += gp[(size_t)(h0 + RAD - 1) * WW];
    t2 += gp[(size_t)(h0 + RAD) * WW];

    float s = (t0 + t1) + (t2 + t3);

    // branch-free sliding window (halo rows are zero)
    #pragma unroll
    for (int i = 0; i < HT; ++i) {
        const int h = h0 + i;
        op[(size_t)h * WW] = s;
        s += gp[(size_t)(h + RAD + 1) * WW] - gp[(size_t)(h - RAD) * WW];
    }
}

// ---------------------------------------------------------------------------

extern "C" void kernel_launch(void* const* d_in, const int* in_sizes, int n_in,
                              void* d_out, int out_size) {
    const float* x = (const float*)d_in[0];
    float* out = (float*)d_out;

    const int n = in_sizes[0];
    const int B = n / (CCH * HH * WW);   // 4

    dim3 gridA(HH / RPB, B);
    grad_boxw_kernel<<<gridA, 256>>>(x);

    dim3 gridB(WW / 256, HH / HT, B);
    boxh_kernel<<<gridB, 256>>>(out);
}